// round 1
// baseline (speedup 1.0000x reference)
#include <cuda_runtime.h>
#include <cuda_bf16.h>
#include <cstdint>

// Problem constants
#define TOKENS 4096
#define IN_F   4096
#define OUT_F  11008
#define GROUP  128
#define NGRP   32          // IN_F / GROUP
#define BYTES_PER_ROW 2048 // IN_F/2 packed bytes per out-channel (one int32 per byte)

// Tile config
#define BM 128
#define BN 128
#define BK 16
#define NTHREADS 256

// ---------------- packed f32x2 helpers (Blackwell FFMA2 path) ----------------
__device__ __forceinline__ void ffma2(unsigned long long& d,
                                      unsigned long long a,
                                      unsigned long long b) {
    asm("fma.rn.f32x2 %0, %1, %2, %0;" : "+l"(d) : "l"(a), "l"(b));
}
__device__ __forceinline__ unsigned long long splat2(float v) {
    unsigned long long r;
    asm("mov.b64 %0, {%1, %1};" : "=l"(r) : "f"(v));
    return r;
}
__device__ __forceinline__ void unpack2(unsigned long long v, float& lo, float& hi) {
    asm("mov.b64 {%0, %1}, %2;" : "=f"(lo), "=f"(hi) : "l"(v));
}

// y[m][n] = sum_k x[m][k] * (sint4(w[n][k]) - zero[n][k/128]) * scale[n][k/128]
__global__ void __launch_bounds__(NTHREADS, 2)
int4_gemm_kernel(const float* __restrict__ x,
                 const int*   __restrict__ wp,   // packed bytes, one per int32
                 const float* __restrict__ ws,   // [OUT_F, NGRP]
                 const int*   __restrict__ wz,   // [OUT_F, NGRP]
                 float*       __restrict__ y)
{
    __shared__ float As[BK][BM + 4];   // [k][m], padded
    __shared__ float Bs[BK][BN + 4];   // [k][n], padded

    const int tid  = threadIdx.x;
    const int tx   = tid & 15;         // n micro index (8 cols -> 4 f32x2 pairs)
    const int ty   = tid >> 4;         // m micro index (8 rows)
    const int n0   = blockIdx.x * BN;
    const int m0   = blockIdx.y * BM;

    // loader mapping: each thread owns one row (128 rows, 2 threads/row)
    const int rl   = tid >> 1;         // 0..127 : row within tile (both A-m and B-n)
    const int half = tid & 1;          // which 8-wide k chunk

    const float* x_row  = x  + (size_t)(m0 + rl) * IN_F + half * 8;
    const int*   wp_row = wp + (size_t)(n0 + rl) * BYTES_PER_ROW + half * 4;
    const int    sz_row = (n0 + rl) * NGRP;

    unsigned long long c2[8][4];
    #pragma unroll
    for (int i = 0; i < 8; i++)
        #pragma unroll
        for (int j = 0; j < 4; j++) c2[i][j] = 0ull;  // two packed +0.0f

    for (int k0 = 0; k0 < IN_F; k0 += BK) {
        // ---- stage global -> regs ----
        const float4 a0 = *(const float4*)(x_row + k0);
        const float4 a1 = *(const float4*)(x_row + k0 + 4);
        const int4   pb = *(const int4*)(wp_row + (k0 >> 1));
        const int    g  = k0 >> 7;                 // group index (BK divides GROUP)
        const float  s  = ws[sz_row + g];
        const float  z  = (float)wz[sz_row + g];

        __syncthreads();   // previous compute done before overwriting smem

        // ---- A tile (transposed store) ----
        const int kb = half * 8;
        As[kb + 0][rl] = a0.x; As[kb + 1][rl] = a0.y;
        As[kb + 2][rl] = a0.z; As[kb + 3][rl] = a0.w;
        As[kb + 4][rl] = a1.x; As[kb + 5][rl] = a1.y;
        As[kb + 6][rl] = a1.z; As[kb + 7][rl] = a1.w;

        // ---- B tile: dequant 8 nibbles -> fp32 ----
        int bv[4] = {pb.x, pb.y, pb.z, pb.w};
        #pragma unroll
        for (int j = 0; j < 4; j++) {
            const int b  = bv[j];
            const int lo = b & 15;
            const int hi = (b >> 4) & 15;
            // signed int4: (nib ^ 8) - 8 maps 0..15 -> -8..7
            const float wl = ((float)((lo ^ 8) - 8) - z) * s;
            const float wh = ((float)((hi ^ 8) - 8) - z) * s;
            Bs[kb + 2 * j + 0][rl] = wl;
            Bs[kb + 2 * j + 1][rl] = wh;
        }
        __syncthreads();

        // ---- compute: 8x8 microtile as 8x4 packed f32x2 FMAs ----
        #pragma unroll
        for (int kk = 0; kk < BK; kk++) {
            const float4 av0 = *(const float4*)&As[kk][ty * 8];
            const float4 av1 = *(const float4*)&As[kk][ty * 8 + 4];
            const unsigned long long* bp =
                (const unsigned long long*)&Bs[kk][tx * 8];
            unsigned long long b2[4];
            #pragma unroll
            for (int j = 0; j < 4; j++) b2[j] = bp[j];

            const float a_[8] = {av0.x, av0.y, av0.z, av0.w,
                                 av1.x, av1.y, av1.z, av1.w};
            #pragma unroll
            for (int i = 0; i < 8; i++) {
                const unsigned long long a2 = splat2(a_[i]);
                #pragma unroll
                for (int j = 0; j < 4; j++) ffma2(c2[i][j], a2, b2[j]);
            }
        }
    }

    // ---- epilogue ----
    #pragma unroll
    for (int i = 0; i < 8; i++) {
        float* yr = y + (size_t)(m0 + ty * 8 + i) * OUT_F + n0 + tx * 8;
        #pragma unroll
        for (int j = 0; j < 4; j++) {
            float lo, hi;
            unpack2(c2[i][j], lo, hi);
            *(float2*)(yr + 2 * j) = make_float2(lo, hi);
        }
    }
}

extern "C" void kernel_launch(void* const* d_in, const int* in_sizes, int n_in,
                              void* d_out, int out_size)
{
    const float* x  = (const float*)d_in[0];
    const int*   wp = (const int*)d_in[1];
    const float* ws = (const float*)d_in[2];
    const int*   wz = (const int*)d_in[3];
    float*       y  = (float*)d_out;

    dim3 grid(OUT_F / BN, TOKENS / BM);   // (86, 32) — exact tiling, no bounds checks
    int4_gemm_kernel<<<grid, NTHREADS>>>(x, wp, ws, wz, y);
}

// round 4
// speedup vs baseline: 2.2851x; 2.2851x over previous
#include <cuda_runtime.h>
#include <cstdint>

// ---------------- problem constants ----------------
#define TOKENS 4096
#define IN_F   4096
#define OUT_F  11008
#define NGRP   32
#define INTS_PER_ROW 2048     // one packed BYTE per int32 -> IN/2 ints per out-channel

// ---------------- tile config ----------------
#define BM 128
#define BN 128
#define BK 32
#define NITER (IN_F / BK)     // 128
#define NTHREADS 256

// A smem block (16m x 8k): 4 planes x 36 floats  -> a_j at blk*ABLK + j*36 + lane
#define ABLK 144
#define ASTAGE (32 * ABLK)    // 32 blocks (4 ks x 8 mfrag) = 4608 floats
// B smem block (8n x 8k): 2 planes x 36 floats   -> b_j at blk*BBLK + j*36 + lane
#define BBLK 72
#define BSTAGE (64 * BBLK)    // 64 blocks (4 ks x 16 nfrag) = 4608 floats
#define SMEM_BYTES ((2 * ASTAGE + 2 * BSTAGE) * 4)   // 73728 B

__device__ __forceinline__ uint32_t tf32r(float f) {   // round-to-nearest tf32
    uint32_t r; asm("cvt.rna.tf32.f32 %0, %1;" : "=r"(r) : "f"(f)); return r;
}
__device__ __forceinline__ float tf32f(float f) { return __uint_as_float(tf32r(f)); }

__device__ __forceinline__ void mma8(float& d0, float& d1, float& d2, float& d3,
                                     uint32_t a0, uint32_t a1, uint32_t a2, uint32_t a3,
                                     uint32_t b0, uint32_t b1) {
    asm volatile("mma.sync.aligned.m16n8k8.row.col.f32.tf32.tf32.f32 "
                 "{%0,%1,%2,%3}, {%4,%5,%6,%7}, {%8,%9}, {%0,%1,%2,%3};"
                 : "+f"(d0), "+f"(d1), "+f"(d2), "+f"(d3)
                 : "r"(a0), "r"(a1), "r"(a2), "r"(a3), "r"(b0), "r"(b1));
}

__global__ void __launch_bounds__(NTHREADS, 1)
int4_mma_kernel(const float* __restrict__ x,
                const int*   __restrict__ wp,
                const float* __restrict__ ws,
                const int*   __restrict__ wz,
                float*       __restrict__ y)
{
    extern __shared__ float sm[];
    float* Asm = sm;                   // 2 stages of ASTAGE
    float* Bsm = sm + 2 * ASTAGE;      // 2 stages of BSTAGE

    const int tid  = threadIdx.x;
    const int lane = tid & 31;
    const int wid  = tid >> 5;
    const int warprow = wid >> 2;      // 0..1 (64 m-rows each)
    const int warpcol = wid & 3;       // 0..3 (32 n-cols each)
    const int g = lane >> 2;           // 0..7
    const int t = lane & 3;            // 0..3
    const int n0 = blockIdx.x * BN;
    const int m0 = blockIdx.y * BM;

    // ---- A loader: thread -> (row r, half ha), 16 k-values per iter ----
    const int r  = tid >> 1;
    const int ha = tid & 1;
    const float4* xp = (const float4*)(x + (size_t)(m0 + r) * IN_F + ha * 16);
    const int ph = (r >> 3) & 1;
    const int aw0 = ((2 * ha) * 8 + (r >> 4)) * ABLK + ph * 36 + (r & 7) * 4;

    // ---- B loader: thread -> (col c, half hb), 16 nibbles (8 ints) per iter ----
    const int c  = tid >> 1;
    const int hb = tid & 1;
    const uint4* wpq = (const uint4*)(wp + (size_t)(n0 + c) * INTS_PER_ROW + hb * 8);
    const float* wsrow = ws + (size_t)(n0 + c) * NGRP;
    const int*   wzrow = wz + (size_t)(n0 + c) * NGRP;
    const int bw0 = ((2 * hb) * 16 + (c >> 3)) * BBLK + (c & 7) * 4;

    float acc[4][4][4];
    #pragma unroll
    for (int mf = 0; mf < 4; mf++)
        #pragma unroll
        for (int f = 0; f < 4; f++)
            #pragma unroll
            for (int q = 0; q < 4; q++) acc[mf][f][q] = 0.0f;

    // ---- prologue prefetch (iter 0) ----
    float4 xa[4];
    #pragma unroll
    for (int q = 0; q < 4; q++) xa[q] = xp[q];
    uint4 bu0 = wpq[0], bu1 = wpq[1];
    float sc = wsrow[0];
    float cc = (-8.0f - (float)wzrow[0]) * sc;

    for (int i = 0; i < NITER; i++) {
        const int sa = (i & 1) * ASTAGE;
        const int sb = (i & 1) * BSTAGE;

        // ---- stage A (tf32-rounded, vectorized) ----
        *(float4*)&Asm[sa + aw0           ] = make_float4(tf32f(xa[0].x), tf32f(xa[0].y), tf32f(xa[0].z), tf32f(xa[0].w));
        *(float4*)&Asm[sa + aw0 + 72      ] = make_float4(tf32f(xa[1].x), tf32f(xa[1].y), tf32f(xa[1].z), tf32f(xa[1].w));
        *(float4*)&Asm[sa + aw0 + 8 * ABLK] = make_float4(tf32f(xa[2].x), tf32f(xa[2].y), tf32f(xa[2].z), tf32f(xa[2].w));
        *(float4*)&Asm[sa + aw0 + 8 * ABLK + 72] = make_float4(tf32f(xa[3].x), tf32f(xa[3].y), tf32f(xa[3].z), tf32f(xa[3].w));

        // ---- stage B: dequant 16 nibbles (8 ints, one byte each) ----
        {
            const uint32_t bw[8] = {bu0.x, bu0.y, bu0.z, bu0.w, bu1.x, bu1.y, bu1.z, bu1.w};
            float wv[16];
            #pragma unroll
            for (int j = 0; j < 8; j++) {
                const uint32_t lo = (bw[j] & 15u) ^ 8u;
                const uint32_t hi = ((bw[j] >> 4) & 15u) ^ 8u;
                wv[2 * j + 0] = tf32f(fmaf((float)(int)lo, sc, cc));
                wv[2 * j + 1] = tf32f(fmaf((float)(int)hi, sc, cc));
            }
            *(float4*)&Bsm[sb + bw0               ] = make_float4(wv[0],  wv[1],  wv[2],  wv[3]);
            *(float4*)&Bsm[sb + bw0 + 36          ] = make_float4(wv[4],  wv[5],  wv[6],  wv[7]);
            *(float4*)&Bsm[sb + bw0 + 16 * BBLK   ] = make_float4(wv[8],  wv[9],  wv[10], wv[11]);
            *(float4*)&Bsm[sb + bw0 + 16 * BBLK + 36] = make_float4(wv[12], wv[13], wv[14], wv[15]);
        }

        // ---- prefetch next iter ----
        if (i + 1 < NITER) {
            #pragma unroll
            for (int q = 0; q < 4; q++) xa[q] = xp[(i + 1) * 8 + q];
            bu0 = wpq[(i + 1) * 4 + 0];
            bu1 = wpq[(i + 1) * 4 + 1];
            if (((i + 1) & 3) == 0) {            // group boundary (128 k)
                const int gg = (i + 1) >> 2;
                sc = wsrow[gg];
                cc = (-8.0f - (float)wzrow[gg]) * sc;
            }
        }

        __syncthreads();

        // ---- compute: 4 k-steps x (4 mfrag x 4 nfrag) m16n8k8 ----
        #pragma unroll
        for (int ks = 0; ks < 4; ks++) {
            uint32_t a[4][4];
            #pragma unroll
            for (int mf = 0; mf < 4; mf++) {
                const int bb = sa + (ks * 8 + warprow * 4 + mf) * ABLK + lane;
                #pragma unroll
                for (int j = 0; j < 4; j++)
                    a[mf][j] = __float_as_uint(Asm[bb + j * 36]);
            }
            uint32_t b[4][2];
            #pragma unroll
            for (int f = 0; f < 4; f++) {
                const int bbb = sb + (ks * 16 + warpcol * 4 + f) * BBLK + lane;
                b[f][0] = __float_as_uint(Bsm[bbb]);
                b[f][1] = __float_as_uint(Bsm[bbb + 36]);
            }
            #pragma unroll
            for (int mf = 0; mf < 4; mf++)
                #pragma unroll
                for (int f = 0; f < 4; f++)
                    mma8(acc[mf][f][0], acc[mf][f][1], acc[mf][f][2], acc[mf][f][3],
                         a[mf][0], a[mf][1], a[mf][2], a[mf][3],
                         b[f][0], b[f][1]);
        }
    }

    // ---- epilogue: registers -> gmem ----
    #pragma unroll
    for (int mf = 0; mf < 4; mf++) {
        const int row0 = m0 + warprow * 64 + mf * 16 + g;
        #pragma unroll
        for (int f = 0; f < 4; f++) {
            float* p0 = y + (size_t)row0 * OUT_F + n0 + warpcol * 32 + f * 8 + 2 * t;
            float* p1 = p0 + (size_t)8 * OUT_F;
            *(float2*)p0 = make_float2(acc[mf][f][0], acc[mf][f][1]);
            *(float2*)p1 = make_float2(acc[mf][f][2], acc[mf][f][3]);
        }
    }
}

extern "C" void kernel_launch(void* const* d_in, const int* in_sizes, int n_in,
                              void* d_out, int out_size)
{
    const float* x  = (const float*)d_in[0];
    const int*   wp = (const int*)d_in[1];
    const float* ws = (const float*)d_in[2];
    const int*   wz = (const int*)d_in[3];
    float*       y  = (float*)d_out;

    cudaFuncSetAttribute(int4_mma_kernel,
                         cudaFuncAttributeMaxDynamicSharedMemorySize, SMEM_BYTES);
    dim3 grid(OUT_F / BN, TOKENS / BM);   // (86, 32)
    int4_mma_kernel<<<grid, NTHREADS, SMEM_BYTES>>>(x, wp, ws, wz, y);
}

// round 5
// speedup vs baseline: 3.1064x; 1.3594x over previous
#include <cuda_runtime.h>
#include <cstdint>

// ---------------- problem constants ----------------
#define TOKENS 4096
#define IN_F   4096
#define OUT_F  11008
#define NGRP   32

// ---------------- tile config ----------------
#define BM 128
#define BN 128
#define BK 32
#define NITER (IN_F / BK)       // 128
#define STAGES 3
#define STAGE_FLOATS 4096       // 16KB per operand per stage (BM*BK or BN*BK)
#define TILE_FLOATS (128 * STAGE_FLOATS)   // 524288 floats per (tile, all k)
#define NTHREADS 256

// ---------------- persistent scratch (module-load allocation: allowed) ----------------
__device__ float g_xs[(size_t)TOKENS * IN_F];     // x, tf32-rounded, fragment-tiled
__device__ float g_wd[(size_t)OUT_F * IN_F];      // W, dequantized tf32, fragment-tiled

__device__ __forceinline__ uint32_t tf32r(float f) {
    uint32_t r; asm("cvt.rna.tf32.f32 %0, %1;" : "=r"(r) : "f"(f)); return r;
}
__device__ __forceinline__ float tf32f(float f) { return __uint_as_float(tf32r(f)); }

__device__ __forceinline__ uint32_t smem_u32(const void* p) {
    uint32_t a;
    asm("{ .reg .u64 t; cvta.to.shared.u64 t, %1; cvt.u32.u64 %0, t; }" : "=r"(a) : "l"(p));
    return a;
}
__device__ __forceinline__ void cp16(uint32_t dst, const void* src) {
    asm volatile("cp.async.cg.shared.global [%0], [%1], 16;" :: "r"(dst), "l"(src) : "memory");
}
__device__ __forceinline__ void cp_commit() { asm volatile("cp.async.commit_group;" ::: "memory"); }
__device__ __forceinline__ void cp_wait1()  { asm volatile("cp.async.wait_group 1;" ::: "memory"); }

__device__ __forceinline__ void mma8(float& d0, float& d1, float& d2, float& d3,
                                     uint32_t a0, uint32_t a1, uint32_t a2, uint32_t a3,
                                     uint32_t b0, uint32_t b1) {
    asm volatile("mma.sync.aligned.m16n8k8.row.col.f32.tf32.tf32.f32 "
                 "{%0,%1,%2,%3}, {%4,%5,%6,%7}, {%8,%9}, {%0,%1,%2,%3};"
                 : "+f"(d0), "+f"(d1), "+f"(d2), "+f"(d3)
                 : "r"(a0), "r"(a1), "r"(a2), "r"(a3), "r"(b0), "r"(b1));
}

// ============ prepass 1: round x to tf32, tile into A-fragment order ============
// A block (16m x 8k), 128 floats: addr = plane*32 + (m&7)*4 + (k&3),
// plane = ((m&15)>>3) + 2*((k&7)>>2).  Stage = 32 blocks (blk = kb*8 + mloc>>4).
__global__ void __launch_bounds__(NTHREADS)
prep_x_kernel(const float* __restrict__ x)
{
    const int gid = blockIdx.x * NTHREADS + threadIdx.x;   // granule = 4 consecutive k
    const int kq = gid & 1023;            // IN_F/4 = 1024 granules per row
    const int m  = gid >> 10;
    const float4 v = *(const float4*)(x + ((size_t)m << 12) + (kq << 2));

    const int k0   = kq << 2;
    const int kst  = k0 >> 5;
    const int kloc = k0 & 31;
    const int mt   = m >> 7, mloc = m & 127;
    const int blk  = (kloc >> 3) * 8 + (mloc >> 4);
    const int plane = ((mloc & 15) >> 3) + 2 * ((kloc >> 2) & 1);
    const size_t dst = (size_t)(mt * 128 + kst) * STAGE_FLOATS
                     + blk * 128 + plane * 32 + (mloc & 7) * 4;
    *(float4*)(g_xs + dst) = make_float4(tf32f(v.x), tf32f(v.y), tf32f(v.z), tf32f(v.w));
}

// ============ prepass 2: dequant W to tf32, tile into B-fragment order ============
// B block (8n x 8k), 64 floats: addr = plane*32 + (n&7)*4 + (k&3), plane = (k&7)>>2.
// Stage = 64 blocks (blk = kb*16 + nloc>>3).
__global__ void __launch_bounds__(NTHREADS)
prep_w_kernel(const int*   __restrict__ wp,
              const float* __restrict__ ws,
              const int*   __restrict__ wz)
{
    const int gid = blockIdx.x * NTHREADS + threadIdx.x;   // granule = 4 consecutive k
    const int kq = gid & 1023;
    const int n  = gid >> 10;

    // 4 k-values = 2 packed ints (one byte each; low nibble = even k)
    const int2 pq = *(const int2*)(wp + (size_t)n * 2048 + (kq << 1));
    const int k0 = kq << 2;
    const int grp = k0 >> 7;
    const float s = ws[(size_t)n * NGRP + grp];
    const float c = (-8.0f - (float)wz[(size_t)n * NGRP + grp]) * s;

    float4 o;
    o.x = tf32f(fmaf((float)(int)(((uint32_t)pq.x & 15u) ^ 8u),        s, c));
    o.y = tf32f(fmaf((float)(int)((((uint32_t)pq.x >> 4) & 15u) ^ 8u), s, c));
    o.z = tf32f(fmaf((float)(int)(((uint32_t)pq.y & 15u) ^ 8u),        s, c));
    o.w = tf32f(fmaf((float)(int)((((uint32_t)pq.y >> 4) & 15u) ^ 8u), s, c));

    const int kst  = k0 >> 5;
    const int kloc = k0 & 31;
    const int nt   = n >> 7, nloc = n & 127;
    const int blk  = (kloc >> 3) * 16 + (nloc >> 3);
    const int plane = (kloc >> 2) & 1;
    const size_t dst = (size_t)nt * TILE_FLOATS + (size_t)kst * STAGE_FLOATS
                     + blk * 64 + plane * 32 + (nloc & 7) * 4;
    *(float4*)(g_wd + dst) = o;
}

// ============ main GEMM: pure tf32 MMA, cp.async 3-stage pipeline ============
#define SMEM_BYTES (2 * STAGES * STAGE_FLOATS * 4)   // 98304

__global__ void __launch_bounds__(NTHREADS, 2)
gemm_kernel(float* __restrict__ y)
{
    extern __shared__ float sm[];   // [STAGES][4096] A, then [STAGES][4096] B

    const int tid  = threadIdx.x;
    const int lane = tid & 31;
    const int wid  = tid >> 5;
    const int warprow = wid >> 2;       // 0..1
    const int warpcol = wid & 3;        // 0..3
    const int mt = blockIdx.x;          // m fastest -> 32 m-CTAs of one n-tile co-resident
    const int nt = blockIdx.y;

    const float* Asrc = g_xs + (size_t)mt * TILE_FLOATS + tid * 16;
    const float* Bsrc = g_wd + (size_t)nt * TILE_FLOATS + tid * 16;
    const uint32_t smA = smem_u32(sm) + tid * 64;
    const uint32_t smB = smA + STAGES * STAGE_FLOATS * 4;

    // prologue: fill stages 0..STAGES-2
    #pragma unroll
    for (int i = 0; i < STAGES - 1; i++) {
        const uint32_t da = smA + i * (STAGE_FLOATS * 4);
        const uint32_t db = smB + i * (STAGE_FLOATS * 4);
        const float* sa = Asrc + (size_t)i * STAGE_FLOATS;
        const float* sb = Bsrc + (size_t)i * STAGE_FLOATS;
        #pragma unroll
        for (int j = 0; j < 4; j++) {
            cp16(da + j * 16, sa + j * 4);
            cp16(db + j * 16, sb + j * 4);
        }
        cp_commit();
    }

    float acc[4][4][4];
    #pragma unroll
    for (int mf = 0; mf < 4; mf++)
        #pragma unroll
        for (int f = 0; f < 4; f++)
            #pragma unroll
            for (int q = 0; q < 4; q++) acc[mf][f][q] = 0.0f;

    int st = 0;          // stage index of iter i
    int fs = STAGES - 1; // stage index to fill
    for (int i = 0; i < NITER; i++) {
        cp_wait1();
        __syncthreads();

        // fill stage i+STAGES-1 (safe: its last readers passed the sync above)
        if (i + STAGES - 1 < NITER) {
            const uint32_t da = smA + fs * (STAGE_FLOATS * 4);
            const uint32_t db = smB + fs * (STAGE_FLOATS * 4);
            const float* sa = Asrc + (size_t)(i + STAGES - 1) * STAGE_FLOATS;
            const float* sb = Bsrc + (size_t)(i + STAGES - 1) * STAGE_FLOATS;
            #pragma unroll
            for (int j = 0; j < 4; j++) {
                cp16(da + j * 16, sa + j * 4);
                cp16(db + j * 16, sb + j * 4);
            }
        }
        cp_commit();   // one group per iter (empty near tail keeps accounting uniform)

        const float* As = sm + st * STAGE_FLOATS;
        const float* Bs = sm + STAGES * STAGE_FLOATS + st * STAGE_FLOATS;

        #pragma unroll
        for (int ks = 0; ks < 4; ks++) {
            uint32_t a[4][4];
            #pragma unroll
            for (int mf = 0; mf < 4; mf++) {
                const int bb = (ks * 8 + warprow * 4 + mf) * 128 + lane;
                #pragma unroll
                for (int j = 0; j < 4; j++)
                    a[mf][j] = __float_as_uint(As[bb + j * 32]);
            }
            uint32_t b[4][2];
            #pragma unroll
            for (int f = 0; f < 4; f++) {
                const int bb = (ks * 16 + warpcol * 4 + f) * 64 + lane;
                b[f][0] = __float_as_uint(Bs[bb]);
                b[f][1] = __float_as_uint(Bs[bb + 32]);
            }
            #pragma unroll
            for (int mf = 0; mf < 4; mf++)
                #pragma unroll
                for (int f = 0; f < 4; f++)
                    mma8(acc[mf][f][0], acc[mf][f][1], acc[mf][f][2], acc[mf][f][3],
                         a[mf][0], a[mf][1], a[mf][2], a[mf][3],
                         b[f][0], b[f][1]);
        }

        st = (st + 1 == STAGES) ? 0 : st + 1;
        fs = (fs + 1 == STAGES) ? 0 : fs + 1;
    }

    // ---- epilogue ----
    const int g = lane >> 2, t = lane & 3;
    const int m0 = mt * BM, n0 = nt * BN;
    #pragma unroll
    for (int mf = 0; mf < 4; mf++) {
        const int row0 = m0 + warprow * 64 + mf * 16 + g;
        #pragma unroll
        for (int f = 0; f < 4; f++) {
            float* p0 = y + (size_t)row0 * OUT_F + n0 + warpcol * 32 + f * 8 + 2 * t;
            float* p1 = p0 + (size_t)8 * OUT_F;
            *(float2*)p0 = make_float2(acc[mf][f][0], acc[mf][f][1]);
            *(float2*)p1 = make_float2(acc[mf][f][2], acc[mf][f][3]);
        }
    }
}

extern "C" void kernel_launch(void* const* d_in, const int* in_sizes, int n_in,
                              void* d_out, int out_size)
{
    const float* x  = (const float*)d_in[0];
    const int*   wp = (const int*)d_in[1];
    const float* ws = (const float*)d_in[2];
    const int*   wz = (const int*)d_in[3];
    float*       y  = (float*)d_out;

    static bool attr_set = false;
    if (!attr_set) {
        cudaFuncSetAttribute(gemm_kernel,
                             cudaFuncAttributeMaxDynamicSharedMemorySize, SMEM_BYTES);
        attr_set = true;
    }

    prep_x_kernel<<<(TOKENS * IN_F / 4) / NTHREADS, NTHREADS>>>(x);
    prep_w_kernel<<<(OUT_F * (IN_F / 4)) / NTHREADS, NTHREADS>>>(wp, ws, wz);
    gemm_kernel<<<dim3(TOKENS / BM, OUT_F / BN), NTHREADS, SMEM_BYTES>>>(y);
}